// round 13
// baseline (speedup 1.0000x reference)
#include <cuda_runtime.h>
#include <cuda_fp16.h>

#define B_     2
#define N_IN_  262144
#define D_     32
#define N_OUT_ 65536
#define K_     4
#define NK_    9
#define TOTAL_ (B_ * N_OUT_ * K_)   // 524288 outputs
#define NROWS_ (B_ * N_IN_)         // 524288 input rows

// Integrated row, 128B stride (one line per row):
// [ 32 x fp16 features (64B) | cx f32, cy f32 (8B) | 8B zero | 32B untouched ]
__device__ uint4 g_xrow[NROWS_ * 8];   // 64 MB
__device__ float g_uc0;                // 1/(2*sigma^2) when uniform
__device__ int   g_u;                  // 1 = uniform, 2 = general

// ---------------- prep: 8 threads/row, DENSE loads + shfl exchange ----------
// Every lane loads one float4 (512B/warp dense). Slot owners (s<4) pull their
// two float4s via shfl; s=4 loads coords; s=5 writes the sector-pad zero.
__global__ void __launch_bounds__(256) prep_kernel(
    const float* __restrict__ x,      // (B, N_IN, D)
    const float* __restrict__ sigma,  // (D,)
    const float* __restrict__ cin)    // (2, B, N_IN)
{
    const int tid  = blockIdx.x * blockDim.x + threadIdx.x;
    const int r    = tid >> 3;         // row
    const int s    = tid & 7;          // 16B slot
    const unsigned lane = threadIdx.x & 31u;
    const unsigned base = lane & 24u;  // 8-thread group base

    if (blockIdx.x == 0 && threadIdx.x < 32) {
        float sv = sigma[threadIdx.x];
        float c = 1.0f / (2.0f * sv * sv);
        float c0 = __shfl_sync(0xffffffffu, c, 0);
        unsigned same = __ballot_sync(0xffffffffu, c == c0);
        if (threadIdx.x == 0) {
            g_u   = (same == 0xffffffffu) ? 1 : 2;
            g_uc0 = c0;
        }
    }

    // dense: lane loads float4 #s of row r (floats 4s..4s+3)
    float4 q = __ldg(&((const float4*)x)[(size_t)r * 8 + s]);

    // slot s (s<4) needs float4s #2s and #2s+1 -> from lanes base|2(s&3), +1
    const unsigned src0 = base | (2u * (s & 3));
    float ax = __shfl_sync(0xffffffffu, q.x, src0);
    float ay = __shfl_sync(0xffffffffu, q.y, src0);
    float az = __shfl_sync(0xffffffffu, q.z, src0);
    float aw = __shfl_sync(0xffffffffu, q.w, src0);
    float bx = __shfl_sync(0xffffffffu, q.x, src0 + 1);
    float by = __shfl_sync(0xffffffffu, q.y, src0 + 1);
    float bz = __shfl_sync(0xffffffffu, q.z, src0 + 1);
    float bw = __shfl_sync(0xffffffffu, q.w, src0 + 1);

    uint4 v = make_uint4(0u, 0u, 0u, 0u);
    if (s < 4) {
        __half2 h0 = __floats2half2_rn(ax, ay);
        __half2 h1 = __floats2half2_rn(az, aw);
        __half2 h2 = __floats2half2_rn(bx, by);
        __half2 h3 = __floats2half2_rn(bz, bw);
        v.x = *(const unsigned*)&h0;
        v.y = *(const unsigned*)&h1;
        v.z = *(const unsigned*)&h2;
        v.w = *(const unsigned*)&h3;
    } else if (s == 4) {
        v.x = __float_as_uint(__ldg(&cin[r]));
        v.y = __float_as_uint(__ldg(&cin[B_ * N_IN_ + r]));
    }
    if (s < 6) g_xrow[(size_t)r * 8 + s] = v;  // 96B = sectors 0-2, aligned end
}

// ---------------- uniform-sigma hot kernel: integrated rows, 2 batches ------
// Warp = 4 outputs x 8 lanes; lane = 8g + m.
// m=0..3: feature quad; m=4: coord quad (same line, same LDG); m=5..7: idx.
__global__ void __launch_bounds__(256) proj_uniform_kernel(
    const float* __restrict__ cout,   // (2, B, N_OUT, K)
    const int*   __restrict__ nidx,   // (B, N_OUT, K, NK)
    float* __restrict__ out)          // (B, N_OUT*K, D)
{
    if (g_u != 1) return;

    const unsigned lane = threadIdx.x & 31u;
    const int w    = (int)((blockIdx.x * (unsigned)blockDim.x + threadIdx.x) >> 5);
    const int bnk0 = w * 4;
    const int g    = (int)(lane >> 3);
    const int m    = (int)(lane & 7u);
    const int bnk  = bnk0 + g;
    const int b    = bnk0 >> 18;
    const unsigned gb = lane & 24u;

    // neighbor indices: lanes m=5,6,7 hold idx[m-5], idx[m-2], idx[m+1]
    int i0 = 0, i1 = 0, i2 = 0;
    if (m >= 5) {
        const size_t nb = (size_t)bnk * NK_ + (m - 5);
        i0 = __ldg(&nidx[nb]);
        i1 = __ldg(&nidx[nb + 3]);
        i2 = __ldg(&nidx[nb + 6]);
    }

    float ox = 0.0f, oy = 0.0f;
    if (m == 4) {
        ox = __ldg(&cout[bnk]);
        oy = __ldg(&cout[bnk + TOTAL_]);
    }

    const uint4* base = g_xrow + (size_t)b * N_IN_ * 8 + m;
    const float cu = g_uc0;

    float a0 = 0.f, a1 = 0.f, a2 = 0.f, a3 = 0.f;
    float a4 = 0.f, a5 = 0.f, a6 = 0.f, a7 = 0.f;
    float den = 1e-9f;

    // ---------- batch A: j = 0..4 ----------
    {
        int ij[5];
#pragma unroll
        for (int j = 0; j < 5; j++) {
            int v = (j < 3) ? i0 : i1;
            ij[j] = __shfl_sync(0xffffffffu, v, (int)(gb | (5u + (j % 3))));
        }
        uint4 f[5];
#pragma unroll
        for (int j = 0; j < 5; j++) {
            if (m < 5) f[j] = __ldg(base + (size_t)ij[j] * 8);
            else       f[j] = make_uint4(0u, 0u, 0u, 0u);
        }
        float e[5];
#pragma unroll
        for (int j = 0; j < 5; j++) {
            float dx = ox - __uint_as_float(f[j].x);
            float dy = oy - __uint_as_float(f[j].y);
            e[j] = __expf(-(dx * dx + dy * dy) * cu);
        }
#pragma unroll
        for (int j = 0; j < 5; j++) {
            float wj = __shfl_sync(0xffffffffu, e[j], (int)(gb | 4u));
            float2 p0 = __half22float2(*(const __half2*)&f[j].x);
            float2 p1 = __half22float2(*(const __half2*)&f[j].y);
            float2 p2 = __half22float2(*(const __half2*)&f[j].z);
            float2 p3 = __half22float2(*(const __half2*)&f[j].w);
            a0 = fmaf(wj, p0.x, a0);  a1 = fmaf(wj, p0.y, a1);
            a2 = fmaf(wj, p1.x, a2);  a3 = fmaf(wj, p1.y, a3);
            a4 = fmaf(wj, p2.x, a4);  a5 = fmaf(wj, p2.y, a5);
            a6 = fmaf(wj, p3.x, a6);  a7 = fmaf(wj, p3.y, a7);
            den += wj;
        }
    }

    // ---------- batch B: j = 5..8 ----------
    {
        int ij[4];
#pragma unroll
        for (int jj = 0; jj < 4; jj++) {
            int j = jj + 5;
            int v = (j < 6) ? i1 : i2;
            ij[jj] = __shfl_sync(0xffffffffu, v, (int)(gb | (5u + (j % 3))));
        }
        uint4 f[4];
#pragma unroll
        for (int jj = 0; jj < 4; jj++) {
            if (m < 5) f[jj] = __ldg(base + (size_t)ij[jj] * 8);
            else       f[jj] = make_uint4(0u, 0u, 0u, 0u);
        }
        float e[4];
#pragma unroll
        for (int jj = 0; jj < 4; jj++) {
            float dx = ox - __uint_as_float(f[jj].x);
            float dy = oy - __uint_as_float(f[jj].y);
            e[jj] = __expf(-(dx * dx + dy * dy) * cu);
        }
#pragma unroll
        for (int jj = 0; jj < 4; jj++) {
            float wj = __shfl_sync(0xffffffffu, e[jj], (int)(gb | 4u));
            float2 p0 = __half22float2(*(const __half2*)&f[jj].x);
            float2 p1 = __half22float2(*(const __half2*)&f[jj].y);
            float2 p2 = __half22float2(*(const __half2*)&f[jj].z);
            float2 p3 = __half22float2(*(const __half2*)&f[jj].w);
            a0 = fmaf(wj, p0.x, a0);  a1 = fmaf(wj, p0.y, a1);
            a2 = fmaf(wj, p1.x, a2);  a3 = fmaf(wj, p1.y, a3);
            a4 = fmaf(wj, p2.x, a4);  a5 = fmaf(wj, p2.y, a5);
            a6 = fmaf(wj, p3.x, a6);  a7 = fmaf(wj, p3.y, a7);
            den += wj;
        }
    }

    if (m < 4) {
        float inv = __fdividef(1.0f, den);
        float* dst = out + (size_t)bnk * D_ + m * 8;
        ((float4*)dst)[0] = make_float4(a0 * inv, a1 * inv, a2 * inv, a3 * inv);
        ((float4*)dst)[1] = make_float4(a4 * inv, a5 * inv, a6 * inv, a7 * inv);
    }
}

// ---------------- general-sigma fallback: grid-strided, dead when uniform ---
__global__ void __launch_bounds__(256) proj_general_kernel(
    const float* __restrict__ cout,
    const float* __restrict__ sigma,
    const int*   __restrict__ nidx,
    float* __restrict__ out)
{
    if (g_u == 1) return;

    const unsigned lane = threadIdx.x & 31u;
    const int nwarps_total = TOTAL_ / 4;
    const int warps_per_grid = (int)((gridDim.x * blockDim.x) >> 5);

    for (int w = (int)((blockIdx.x * (unsigned)blockDim.x + threadIdx.x) >> 5);
         w < nwarps_total; w += warps_per_grid) {
        const int bnk0 = w * 4;
        const int g    = (int)(lane >> 3);
        const int sl   = (int)(lane & 7u);
        const int bnk  = bnk0 + g;
        const int b    = bnk0 >> 18;

        int   idxA = 0, idxB = 0;
        float tA = 0.0f, tB = 0.0f;
        if (lane < 2 * NK_) {
            const int o = (lane >= NK_) ? 1 : 0;
            const int j = (int)lane - o * NK_;
            const int oA = bnk0 + o;
            idxA = __ldg(&nidx[(size_t)oA * NK_ + j]);
            const int oB = bnk0 + 2 + o;
            idxB = __ldg(&nidx[(size_t)oB * NK_ + j]);
            const float* rowA = (const float*)(g_xrow + ((size_t)b * N_IN_ + idxA) * 8);
            const float* rowB = (const float*)(g_xrow + ((size_t)b * N_IN_ + idxB) * 8);
            float cAx = rowA[16], cAy = rowA[17];
            float cBx = rowB[16], cBy = rowB[17];
            float oxA = __ldg(&cout[oA]);
            float oyA = __ldg(&cout[oA + TOTAL_]);
            float oxB = __ldg(&cout[oB]);
            float oyB = __ldg(&cout[oB + TOTAL_]);
            float dxA = oxA - cAx, dyA = oyA - cAy;
            float dxB = oxB - cBx, dyB = oyB - cBy;
            tA = -(dxA * dxA + dyA * dyA);
            tB = -(dxB * dxB + dyB * dyB);
        }

        const int selbase = (g & 1) * NK_;
        int ij[NK_];
#pragma unroll
        for (int j = 0; j < NK_; j++) {
            int a  = __shfl_sync(0xffffffffu, idxA, selbase + j);
            int bb = __shfl_sync(0xffffffffu, idxB, selbase + j);
            ij[j] = (g < 2) ? a : bb;
        }

        const uint2* xb = (const uint2*)g_xrow + (size_t)b * N_IN_ * 16 + sl;
        uint2 f[NK_];
#pragma unroll
        for (int j = 0; j < NK_; j++) f[j] = __ldg(xb + (size_t)ij[j] * 16);

        float4 s4 = ((const float4*)sigma)[sl];
        float c0 = 1.0f / (2.0f * s4.x * s4.x);
        float c1 = 1.0f / (2.0f * s4.y * s4.y);
        float c2 = 1.0f / (2.0f * s4.z * s4.z);
        float c3 = 1.0f / (2.0f * s4.w * s4.w);
        float4 num = make_float4(0.f, 0.f, 0.f, 0.f);
        float d0 = 1e-9f, d1 = 1e-9f, d2 = 1e-9f, d3 = 1e-9f;
#pragma unroll
        for (int j = 0; j < NK_; j++) {
            float ta = __shfl_sync(0xffffffffu, tA, selbase + j);
            float tb = __shfl_sync(0xffffffffu, tB, selbase + j);
            float tv = (g < 2) ? ta : tb;
            float w0 = __expf(tv * c0);
            float w1 = __expf(tv * c1);
            float w2 = __expf(tv * c2);
            float w3 = __expf(tv * c3);
            float2 lo = __half22float2(*(const __half2*)&f[j].x);
            float2 hi = __half22float2(*(const __half2*)&f[j].y);
            num.x = fmaf(w0, lo.x, num.x);
            num.y = fmaf(w1, lo.y, num.y);
            num.z = fmaf(w2, hi.x, num.z);
            num.w = fmaf(w3, hi.y, num.w);
            d0 += w0; d1 += w1; d2 += w2; d3 += w3;
        }
        float4 r = make_float4(__fdividef(num.x, d0), __fdividef(num.y, d1),
                               __fdividef(num.z, d2), __fdividef(num.w, d3));
        ((float4*)(out + (size_t)bnk * D_))[sl] = r;
    }
}

extern "C" void kernel_launch(void* const* d_in, const int* in_sizes, int n_in,
                              void* d_out, int out_size) {
    const float* x     = (const float*)d_in[0];
    const float* cin   = (const float*)d_in[1];
    const float* cout  = (const float*)d_in[2];
    const float* sigma = (const float*)d_in[3];
    const int*   nidx  = (const int*)d_in[4];
    float* out = (float*)d_out;

    prep_kernel<<<(NROWS_ * 8) / 256, 256>>>(x, sigma, cin);
    proj_uniform_kernel<<<TOTAL_ / 4 / 8, 256>>>(cout, nidx, out);
    proj_general_kernel<<<1184, 256>>>(cout, sigma, nidx, out);
}

// round 14
// speedup vs baseline: 1.4749x; 1.4749x over previous
#include <cuda_runtime.h>

#define B_     2
#define N_IN_  262144
#define D_     32
#define N_OUT_ 65536
#define K_     4
#define NK_    9
#define TOTAL_ (B_ * N_OUT_ * K_)   // 524288 outputs

// sigma-dedup results + interleaved coords
__device__ float  g_uc0;              // 1/(2*sigma^2) when uniform
__device__ int    g_u;                // 1 = uniform sigma, 2 = general
__device__ float2 g_c2[B_ * N_IN_];   // (cx, cy) per input point

// Minimal prep: sigma uniformity check + coord interleave (~2 us, measured R8).
__global__ void __launch_bounds__(256) prep_kernel(
    const float* __restrict__ sigma, const float* __restrict__ cin)
{
    const int tid = blockIdx.x * blockDim.x + threadIdx.x;

    if (blockIdx.x == 0 && threadIdx.x < 32) {
        float s = sigma[threadIdx.x];
        float c = 1.0f / (2.0f * s * s);
        float c0 = __shfl_sync(0xffffffffu, c, 0);
        unsigned same = __ballot_sync(0xffffffffu, c == c0);
        if (threadIdx.x == 0) {
            g_u   = (same == 0xffffffffu) ? 1 : 2;
            g_uc0 = c0;
        }
    }

    if (tid < (B_ * N_IN_) / 4) {
        float4 cx = __ldg(&((const float4*)cin)[tid]);
        float4 cy = __ldg(&((const float4*)(cin + B_ * N_IN_))[tid]);
        float4* dst = (float4*)g_c2;
        dst[tid * 2 + 0] = make_float4(cx.x, cy.x, cx.y, cy.y);
        dst[tid * 2 + 1] = make_float4(cx.z, cy.z, cx.w, cy.w);
    }
}

// ---------------- uniform-sigma hot kernel: R8 proj body, general branch
// stripped. Warp = 4 outputs; g = lane>>3 (output), sl = lane&7 (channel quad).
__global__ void __launch_bounds__(256) proj_uniform_kernel(
    const float* __restrict__ x,      // (B, N_IN, D)
    const float* __restrict__ cout,   // (2, B, N_OUT, K)
    const int*   __restrict__ nidx,   // (B, N_OUT, K, NK)
    float* __restrict__ out)          // (B, N_OUT*K, D)
{
    if (g_u != 1) return;

    const unsigned lane = threadIdx.x & 31u;
    const int w    = (int)((blockIdx.x * (unsigned)blockDim.x + threadIdx.x) >> 5);
    const int bnk0 = w * 4;
    const int g    = (int)(lane >> 3);
    const int sl   = (int)(lane & 7u);
    const int bnk  = bnk0 + g;
    const int b    = bnk0 >> 18;

    // lanes 0..17: (output o, neighbor j), phases A (outputs 0,1) / B (2,3)
    int   idxA = 0, idxB = 0;
    float tA = 0.0f, tB = 0.0f;
    if (lane < 2 * NK_) {
        const int o = (lane >= NK_) ? 1 : 0;
        const int j = (int)lane - o * NK_;

        const int oA = bnk0 + o;
        idxA = __ldg(&nidx[(size_t)oA * NK_ + j]);
        const int oB = bnk0 + 2 + o;
        idxB = __ldg(&nidx[(size_t)oB * NK_ + j]);

        float2 cA = g_c2[b * N_IN_ + idxA];
        float2 cB = g_c2[b * N_IN_ + idxB];
        float oxA = __ldg(&cout[oA]);
        float oyA = __ldg(&cout[oA + TOTAL_]);
        float oxB = __ldg(&cout[oB]);
        float oyB = __ldg(&cout[oB + TOTAL_]);

        float dxA = oxA - cA.x, dyA = oyA - cA.y;
        float dxB = oxB - cB.x, dyB = oyB - cB.y;
        tA = -(dxA * dxA + dyA * dyA);
        tB = -(dxB * dxB + dyB * dyB);
    }

    // idx broadcast first, then batched gathers (MLP = 9) — proven structure
    const int selbase = (g & 1) * NK_;
    int ij[NK_];
#pragma unroll
    for (int j = 0; j < NK_; j++) {
        int a  = __shfl_sync(0xffffffffu, idxA, selbase + j);
        int bb = __shfl_sync(0xffffffffu, idxB, selbase + j);
        ij[j] = (g < 2) ? a : bb;
    }

    const float4* xb = (const float4*)(x + (size_t)b * N_IN_ * D_) + sl;
    float4 f[NK_];
#pragma unroll
    for (int j = 0; j < NK_; j++) f[j] = __ldg(xb + (size_t)ij[j] * (D_ / 4));

    // 2 MUFU passes warp-wide cover all 36 weights; overlapped with gathers
    float eA = __expf(tA * g_uc0);
    float eB = __expf(tB * g_uc0);

    float4 num = make_float4(0.f, 0.f, 0.f, 0.f);
    float den = 1e-9f;
#pragma unroll
    for (int j = 0; j < NK_; j++) {
        float ea = __shfl_sync(0xffffffffu, eA, selbase + j);
        float eb = __shfl_sync(0xffffffffu, eB, selbase + j);
        float wj = (g < 2) ? ea : eb;
        num.x = fmaf(wj, f[j].x, num.x);
        num.y = fmaf(wj, f[j].y, num.y);
        num.z = fmaf(wj, f[j].z, num.z);
        num.w = fmaf(wj, f[j].w, num.w);
        den += wj;
    }
    float inv = __fdividef(1.0f, den);
    float4 r = make_float4(num.x * inv, num.y * inv, num.z * inv, num.w * inv);
    ((float4*)(out + (size_t)bnk * D_))[sl] = r;
}

// ---------------- general-sigma fallback: grid-strided, dead when uniform ---
__global__ void __launch_bounds__(256) proj_general_kernel(
    const float* __restrict__ x,
    const float* __restrict__ cout,
    const float* __restrict__ sigma,
    const int*   __restrict__ nidx,
    float* __restrict__ out)
{
    if (g_u == 1) return;

    const unsigned lane = threadIdx.x & 31u;
    const int nwarps_total = TOTAL_ / 4;
    const int warps_per_grid = (int)((gridDim.x * blockDim.x) >> 5);

    for (int w = (int)((blockIdx.x * (unsigned)blockDim.x + threadIdx.x) >> 5);
         w < nwarps_total; w += warps_per_grid) {
        const int bnk0 = w * 4;
        const int g    = (int)(lane >> 3);
        const int sl   = (int)(lane & 7u);
        const int bnk  = bnk0 + g;
        const int b    = bnk0 >> 18;

        int   idxA = 0, idxB = 0;
        float tA = 0.0f, tB = 0.0f;
        if (lane < 2 * NK_) {
            const int o = (lane >= NK_) ? 1 : 0;
            const int j = (int)lane - o * NK_;
            const int oA = bnk0 + o;
            idxA = __ldg(&nidx[(size_t)oA * NK_ + j]);
            const int oB = bnk0 + 2 + o;
            idxB = __ldg(&nidx[(size_t)oB * NK_ + j]);
            float2 cA = g_c2[b * N_IN_ + idxA];
            float2 cB = g_c2[b * N_IN_ + idxB];
            float oxA = __ldg(&cout[oA]);
            float oyA = __ldg(&cout[oA + TOTAL_]);
            float oxB = __ldg(&cout[oB]);
            float oyB = __ldg(&cout[oB + TOTAL_]);
            float dxA = oxA - cA.x, dyA = oyA - cA.y;
            float dxB = oxB - cB.x, dyB = oyB - cB.y;
            tA = -(dxA * dxA + dyA * dyA);
            tB = -(dxB * dxB + dyB * dyB);
        }

        const int selbase = (g & 1) * NK_;
        int ij[NK_];
#pragma unroll
        for (int j = 0; j < NK_; j++) {
            int a  = __shfl_sync(0xffffffffu, idxA, selbase + j);
            int bb = __shfl_sync(0xffffffffu, idxB, selbase + j);
            ij[j] = (g < 2) ? a : bb;
        }

        const float4* xb = (const float4*)(x + (size_t)b * N_IN_ * D_) + sl;
        float4 f[NK_];
#pragma unroll
        for (int j = 0; j < NK_; j++) f[j] = __ldg(xb + (size_t)ij[j] * (D_ / 4));

        float4 s4 = ((const float4*)sigma)[sl];
        float c0 = 1.0f / (2.0f * s4.x * s4.x);
        float c1 = 1.0f / (2.0f * s4.y * s4.y);
        float c2 = 1.0f / (2.0f * s4.z * s4.z);
        float c3 = 1.0f / (2.0f * s4.w * s4.w);
        float4 num = make_float4(0.f, 0.f, 0.f, 0.f);
        float d0 = 1e-9f, d1 = 1e-9f, d2 = 1e-9f, d3 = 1e-9f;
#pragma unroll
        for (int j = 0; j < NK_; j++) {
            float ta = __shfl_sync(0xffffffffu, tA, selbase + j);
            float tb = __shfl_sync(0xffffffffu, tB, selbase + j);
            float tv = (g < 2) ? ta : tb;
            float w0 = __expf(tv * c0);
            float w1 = __expf(tv * c1);
            float w2 = __expf(tv * c2);
            float w3 = __expf(tv * c3);
            num.x = fmaf(w0, f[j].x, num.x);
            num.y = fmaf(w1, f[j].y, num.y);
            num.z = fmaf(w2, f[j].z, num.z);
            num.w = fmaf(w3, f[j].w, num.w);
            d0 += w0; d1 += w1; d2 += w2; d3 += w3;
        }
        float4 r = make_float4(__fdividef(num.x, d0), __fdividef(num.y, d1),
                               __fdividef(num.z, d2), __fdividef(num.w, d3));
        ((float4*)(out + (size_t)bnk * D_))[sl] = r;
    }
}

extern "C" void kernel_launch(void* const* d_in, const int* in_sizes, int n_in,
                              void* d_out, int out_size) {
    const float* x     = (const float*)d_in[0];
    const float* cin   = (const float*)d_in[1];
    const float* cout  = (const float*)d_in[2];
    const float* sigma = (const float*)d_in[3];
    const int*   nidx  = (const int*)d_in[4];
    float* out = (float*)d_out;

    const int prep_items = (B_ * N_IN_) / 4;                    // 131072
    prep_kernel<<<(prep_items + 255) / 256, 256>>>(sigma, cin);

    // hot path: 4 outputs/warp -> 131072 warps -> 16384 blocks
    proj_uniform_kernel<<<TOTAL_ / 4 / 8, 256>>>(x, cout, nidx, out);
    // fallback: grid-strided, ~nothing when sigma uniform
    proj_general_kernel<<<1184, 256>>>(x, cout, sigma, nidx, out);
}

// round 15
// speedup vs baseline: 1.4756x; 1.0005x over previous
#include <cuda_runtime.h>

#define B_     2
#define N_IN_  262144
#define D_     32
#define N_OUT_ 65536
#define K_     4
#define NK_    9
#define TOTAL_ (B_ * N_OUT_ * K_)   // 524288 outputs

// sigma-dedup results + interleaved coords
__device__ float  g_uc0;              // 1/(2*sigma^2) when uniform
__device__ int    g_u;                // 1 = uniform sigma, 2 = general
__device__ float2 g_c2[B_ * N_IN_];   // (cx, cy) per input point

// Minimal prep: one point per thread, fully coalesced (max parallelism).
__global__ void __launch_bounds__(256) prep_kernel(
    const float* __restrict__ sigma, const float* __restrict__ cin)
{
    const int tid = blockIdx.x * blockDim.x + threadIdx.x;

    if (blockIdx.x == 0 && threadIdx.x < 32) {
        float s = sigma[threadIdx.x];
        float c = 1.0f / (2.0f * s * s);
        float c0 = __shfl_sync(0xffffffffu, c, 0);
        unsigned same = __ballot_sync(0xffffffffu, c == c0);
        if (threadIdx.x == 0) {
            g_u   = (same == 0xffffffffu) ? 1 : 2;
            g_uc0 = c0;
        }
    }

    if (tid < B_ * N_IN_) {
        float cx = __ldg(&cin[tid]);
        float cy = __ldg(&cin[B_ * N_IN_ + tid]);
        g_c2[tid] = make_float2(cx, cy);
    }
}

// ---------------- uniform-sigma hot kernel (R14, unchanged) -----------------
// Warp = 4 outputs; g = lane>>3 (output), sl = lane&7 (channel quad).
__global__ void __launch_bounds__(256) proj_uniform_kernel(
    const float* __restrict__ x,      // (B, N_IN, D)
    const float* __restrict__ cout,   // (2, B, N_OUT, K)
    const int*   __restrict__ nidx,   // (B, N_OUT, K, NK)
    float* __restrict__ out)          // (B, N_OUT*K, D)
{
    if (g_u != 1) return;

    const unsigned lane = threadIdx.x & 31u;
    const int w    = (int)((blockIdx.x * (unsigned)blockDim.x + threadIdx.x) >> 5);
    const int bnk0 = w * 4;
    const int g    = (int)(lane >> 3);
    const int sl   = (int)(lane & 7u);
    const int bnk  = bnk0 + g;
    const int b    = bnk0 >> 18;

    // lanes 0..17: (output o, neighbor j), phases A (outputs 0,1) / B (2,3)
    int   idxA = 0, idxB = 0;
    float tA = 0.0f, tB = 0.0f;
    if (lane < 2 * NK_) {
        const int o = (lane >= NK_) ? 1 : 0;
        const int j = (int)lane - o * NK_;

        const int oA = bnk0 + o;
        idxA = __ldg(&nidx[(size_t)oA * NK_ + j]);
        const int oB = bnk0 + 2 + o;
        idxB = __ldg(&nidx[(size_t)oB * NK_ + j]);

        float2 cA = g_c2[b * N_IN_ + idxA];
        float2 cB = g_c2[b * N_IN_ + idxB];
        float oxA = __ldg(&cout[oA]);
        float oyA = __ldg(&cout[oA + TOTAL_]);
        float oxB = __ldg(&cout[oB]);
        float oyB = __ldg(&cout[oB + TOTAL_]);

        float dxA = oxA - cA.x, dyA = oyA - cA.y;
        float dxB = oxB - cB.x, dyB = oyB - cB.y;
        tA = -(dxA * dxA + dyA * dyA);
        tB = -(dxB * dxB + dyB * dyB);
    }

    // idx broadcast first, then batched gathers (MLP = 9) — proven structure
    const int selbase = (g & 1) * NK_;
    int ij[NK_];
#pragma unroll
    for (int j = 0; j < NK_; j++) {
        int a  = __shfl_sync(0xffffffffu, idxA, selbase + j);
        int bb = __shfl_sync(0xffffffffu, idxB, selbase + j);
        ij[j] = (g < 2) ? a : bb;
    }

    const float4* xb = (const float4*)(x + (size_t)b * N_IN_ * D_) + sl;
    float4 f[NK_];
#pragma unroll
    for (int j = 0; j < NK_; j++) f[j] = __ldg(xb + (size_t)ij[j] * (D_ / 4));

    // 2 MUFU passes warp-wide cover all 36 weights; overlapped with gathers
    float eA = __expf(tA * g_uc0);
    float eB = __expf(tB * g_uc0);

    float4 num = make_float4(0.f, 0.f, 0.f, 0.f);
    float den = 1e-9f;
#pragma unroll
    for (int j = 0; j < NK_; j++) {
        float ea = __shfl_sync(0xffffffffu, eA, selbase + j);
        float eb = __shfl_sync(0xffffffffu, eB, selbase + j);
        float wj = (g < 2) ? ea : eb;
        num.x = fmaf(wj, f[j].x, num.x);
        num.y = fmaf(wj, f[j].y, num.y);
        num.z = fmaf(wj, f[j].z, num.z);
        num.w = fmaf(wj, f[j].w, num.w);
        den += wj;
    }
    float inv = __fdividef(1.0f, den);
    float4 r = make_float4(num.x * inv, num.y * inv, num.z * inv, num.w * inv);
    ((float4*)(out + (size_t)bnk * D_))[sl] = r;
}

// ---------------- general-sigma fallback: grid-strided, dead when uniform ---
__global__ void __launch_bounds__(256) proj_general_kernel(
    const float* __restrict__ x,
    const float* __restrict__ cout,
    const float* __restrict__ sigma,
    const int*   __restrict__ nidx,
    float* __restrict__ out)
{
    if (g_u == 1) return;

    const unsigned lane = threadIdx.x & 31u;
    const int nwarps_total = TOTAL_ / 4;
    const int warps_per_grid = (int)((gridDim.x * blockDim.x) >> 5);

    for (int w = (int)((blockIdx.x * (unsigned)blockDim.x + threadIdx.x) >> 5);
         w < nwarps_total; w += warps_per_grid) {
        const int bnk0 = w * 4;
        const int g    = (int)(lane >> 3);
        const int sl   = (int)(lane & 7u);
        const int bnk  = bnk0 + g;
        const int b    = bnk0 >> 18;

        int   idxA = 0, idxB = 0;
        float tA = 0.0f, tB = 0.0f;
        if (lane < 2 * NK_) {
            const int o = (lane >= NK_) ? 1 : 0;
            const int j = (int)lane - o * NK_;
            const int oA = bnk0 + o;
            idxA = __ldg(&nidx[(size_t)oA * NK_ + j]);
            const int oB = bnk0 + 2 + o;
            idxB = __ldg(&nidx[(size_t)oB * NK_ + j]);
            float2 cA = g_c2[b * N_IN_ + idxA];
            float2 cB = g_c2[b * N_IN_ + idxB];
            float oxA = __ldg(&cout[oA]);
            float oyA = __ldg(&cout[oA + TOTAL_]);
            float oxB = __ldg(&cout[oB]);
            float oyB = __ldg(&cout[oB + TOTAL_]);
            float dxA = oxA - cA.x, dyA = oyA - cA.y;
            float dxB = oxB - cB.x, dyB = oyB - cB.y;
            tA = -(dxA * dxA + dyA * dyA);
            tB = -(dxB * dxB + dyB * dyB);
        }

        const int selbase = (g & 1) * NK_;
        int ij[NK_];
#pragma unroll
        for (int j = 0; j < NK_; j++) {
            int a  = __shfl_sync(0xffffffffu, idxA, selbase + j);
            int bb = __shfl_sync(0xffffffffu, idxB, selbase + j);
            ij[j] = (g < 2) ? a : bb;
        }

        const float4* xb = (const float4*)(x + (size_t)b * N_IN_ * D_) + sl;
        float4 f[NK_];
#pragma unroll
        for (int j = 0; j < NK_; j++) f[j] = __ldg(xb + (size_t)ij[j] * (D_ / 4));

        float4 s4 = ((const float4*)sigma)[sl];
        float c0 = 1.0f / (2.0f * s4.x * s4.x);
        float c1 = 1.0f / (2.0f * s4.y * s4.y);
        float c2 = 1.0f / (2.0f * s4.z * s4.z);
        float c3 = 1.0f / (2.0f * s4.w * s4.w);
        float4 num = make_float4(0.f, 0.f, 0.f, 0.f);
        float d0 = 1e-9f, d1 = 1e-9f, d2 = 1e-9f, d3 = 1e-9f;
#pragma unroll
        for (int j = 0; j < NK_; j++) {
            float ta = __shfl_sync(0xffffffffu, tA, selbase + j);
            float tb = __shfl_sync(0xffffffffu, tB, selbase + j);
            float tv = (g < 2) ? ta : tb;
            float w0 = __expf(tv * c0);
            float w1 = __expf(tv * c1);
            float w2 = __expf(tv * c2);
            float w3 = __expf(tv * c3);
            num.x = fmaf(w0, f[j].x, num.x);
            num.y = fmaf(w1, f[j].y, num.y);
            num.z = fmaf(w2, f[j].z, num.z);
            num.w = fmaf(w3, f[j].w, num.w);
            d0 += w0; d1 += w1; d2 += w2; d3 += w3;
        }
        float4 r = make_float4(__fdividef(num.x, d0), __fdividef(num.y, d1),
                               __fdividef(num.z, d2), __fdividef(num.w, d3));
        ((float4*)(out + (size_t)bnk * D_))[sl] = r;
    }
}

extern "C" void kernel_launch(void* const* d_in, const int* in_sizes, int n_in,
                              void* d_out, int out_size) {
    const float* x     = (const float*)d_in[0];
    const float* cin   = (const float*)d_in[1];
    const float* cout  = (const float*)d_in[2];
    const float* sigma = (const float*)d_in[3];
    const int*   nidx  = (const int*)d_in[4];
    float* out = (float*)d_out;

    // prep: one point/thread -> 524288 threads -> 2048 blocks (full chip)
    prep_kernel<<<(B_ * N_IN_ + 255) / 256, 256>>>(sigma, cin);

    // hot path: 4 outputs/warp -> 131072 warps -> 16384 blocks
    proj_uniform_kernel<<<TOTAL_ / 4 / 8, 256>>>(x, cout, nidx, out);
    // fallback: grid-strided; 296 blocks keep the dead-launch cost negligible
    proj_general_kernel<<<296, 256>>>(x, cout, sigma, nidx, out);
}